// round 12
// baseline (speedup 1.0000x reference)
#include <cuda_runtime.h>

#define D      128
#define NN     20000
#define NE     600000
#define ESZ    20

typedef unsigned long long u64;

// ---------------- scratch (device globals; no allocations allowed) ----------
__device__ float g_h1[NN * D];
__device__ float g_so[NN * 3 * D];
__device__ float g_uv[NN * 3 * D];
__device__ float g_vvsq[NN * D];
__device__ float g_ip[NN * D];
__device__ float g_h2[NN * D];

__device__ __forceinline__ float silu_f(float x) {
    return x / (1.0f + __expf(-x));
}
__device__ __forceinline__ u64 pk2(float lo, float hi) {
    u64 r; asm("mov.b64 %0,{%1,%2};" : "=l"(r) : "f"(lo), "f"(hi)); return r;
}
__device__ __forceinline__ void upk2(u64 v, float& lo, float& hi) {
    asm("mov.b64 {%0,%1},%2;" : "=f"(lo), "=f"(hi) : "l"(v));
}
__device__ __forceinline__ u64 fma2(u64 a, u64 b, u64 c) {
    u64 d; asm("fma.rn.f32x2 %0,%1,%2,%3;" : "=l"(d) : "l"(a), "l"(b), "l"(c)); return d;
}
__device__ __forceinline__ u64 mul2(u64 a, u64 b) {
    u64 d; asm("mul.rn.f32x2 %0,%1,%2;" : "=l"(d) : "l"(a), "l"(b)); return d;
}
__device__ __forceinline__ void red4(float* p, float a, float b, float c, float d) {
    asm volatile("red.global.add.v4.f32 [%0], {%1,%2,%3,%4};"
                 :: "l"(p), "f"(a), "f"(b), "f"(c), "f"(d) : "memory");
}
__device__ __forceinline__ void red2(float* p, float a, float b) {
    asm volatile("red.global.add.v2.f32 [%0], {%1,%2};"
                 :: "l"(p), "f"(a), "f"(b) : "memory");
}

// ---------------- kernel 1: init output with residuals -----------------------
__global__ void k_init(const float* __restrict__ ns, const float* __restrict__ nv,
                       float* __restrict__ out) {
    const float4* a = (const float4*)ns;
    const float4* b = (const float4*)nv;
    float4* os = (float4*)out;
    float4* ov = os + (NN * D) / 4;
    const int ts = NN * D / 4;
    const int tv = NN * 3 * D / 4;
    for (int i = blockIdx.x * blockDim.x + threadIdx.x; i < ts; i += gridDim.x * blockDim.x)
        os[i] = a[i];
    for (int i = blockIdx.x * blockDim.x + threadIdx.x; i < tv; i += gridDim.x * blockDim.x)
        ov[i] = b[i];
}

// ---------------- kernel 2: h1 = silu(ns @ Wm1 + bm1) ------------------------
__global__ void __launch_bounds__(512, 1)
k_mlp1(const float* __restrict__ x, const float* __restrict__ W,
       const float* __restrict__ b) {
    extern __shared__ float sm[];
    float* Ws = sm;
    float* bs = sm + 16384;
    int tid = threadIdx.x;
    {
        const float4* Wv = (const float4*)W;
        float4* Wsv = (float4*)Ws;
        for (int i = tid; i < 4096; i += 512) Wsv[i] = Wv[i];
        if (tid < 128) bs[tid] = b[tid];
    }
    __syncthreads();
    int warp = tid >> 5, lane = tid & 31;
    int n0 = blockIdx.x * 64 + warp * 4;

    float xr[4][4];
#pragma unroll
    for (int n = 0; n < 4; n++) {
        int node = n0 + n;
#pragma unroll
        for (int j = 0; j < 4; j++)
            xr[j][n] = (node < NN) ? x[(size_t)node * D + j * 32 + lane] : 0.f;
    }
    ulonglong2 bv = *(const ulonglong2*)(bs + lane * 4);
    u64 al[4], ah[4];
#pragma unroll
    for (int n = 0; n < 4; n++) { al[n] = bv.x; ah[n] = bv.y; }

#pragma unroll
    for (int j = 0; j < 4; j++) {
#pragma unroll
        for (int kk = 0; kk < 32; kk++) {
            int k = j * 32 + kk;
            ulonglong2 w = *(const ulonglong2*)(Ws + k * D + lane * 4);
#pragma unroll
            for (int n = 0; n < 4; n++) {
                float v = __shfl_sync(0xffffffffu, xr[j][n], kk);
                u64 v2 = pk2(v, v);
                al[n] = fma2(v2, w.x, al[n]);
                ah[n] = fma2(v2, w.y, ah[n]);
            }
        }
    }
#pragma unroll
    for (int n = 0; n < 4; n++) {
        int node = n0 + n;
        if (node < NN) {
            float x0, x1, x2, x3;
            upk2(al[n], x0, x1); upk2(ah[n], x2, x3);
            float4 o;
            o.x = silu_f(x0); o.y = silu_f(x1);
            o.z = silu_f(x2); o.w = silu_f(x3);
            *(float4*)(g_h1 + (size_t)node * D + lane * 4) = o;
        }
    }
}

// ---------------- kernel 3: scalar_output = h1 @ Wm2 + bm2  (packed) ---------
__global__ void __launch_bounds__(512, 1)
k_mlp2(const float* __restrict__ W, const float* __restrict__ b) {
    extern __shared__ float sm[];
    float* Ws = sm;                 // 49152
    float* bs = sm + 49152;         // 384
    int tid = threadIdx.x;
    {
        const float4* Wv = (const float4*)W;
        float4* Wsv = (float4*)Ws;
        for (int i = tid; i < 12288; i += 512) Wsv[i] = Wv[i];
        if (tid < 384) bs[tid] = b[tid];
    }
    __syncthreads();
    int warp = tid >> 5, lane = tid & 31;
    int n0 = blockIdx.x * 64 + warp * 4;

    float xr[4][4];
#pragma unroll
    for (int n = 0; n < 4; n++) {
        int node = n0 + n;
#pragma unroll
        for (int j = 0; j < 4; j++)
            xr[j][n] = (node < NN) ? g_h1[(size_t)node * D + j * 32 + lane] : 0.f;
    }
    ulonglong2 b0 = *(const ulonglong2*)(bs + lane * 4);
    ulonglong2 b1 = *(const ulonglong2*)(bs + 128 + lane * 4);
    ulonglong2 b2 = *(const ulonglong2*)(bs + 256 + lane * 4);
    u64 a0l[4], a0h[4], a1l[4], a1h[4], a2l[4], a2h[4];
#pragma unroll
    for (int n = 0; n < 4; n++) {
        a0l[n] = b0.x; a0h[n] = b0.y;
        a1l[n] = b1.x; a1h[n] = b1.y;
        a2l[n] = b2.x; a2h[n] = b2.y;
    }

#pragma unroll
    for (int j = 0; j < 4; j++) {
#pragma unroll
        for (int kk = 0; kk < 32; kk++) {
            int k = j * 32 + kk;
            const float* wp = Ws + k * 384 + lane * 4;
            ulonglong2 w0 = *(const ulonglong2*)wp;
            ulonglong2 w1 = *(const ulonglong2*)(wp + 128);
            ulonglong2 w2 = *(const ulonglong2*)(wp + 256);
#pragma unroll
            for (int n = 0; n < 4; n++) {
                float xv = __shfl_sync(0xffffffffu, xr[j][n], kk);
                u64 xv2 = pk2(xv, xv);
                a0l[n] = fma2(xv2, w0.x, a0l[n]); a0h[n] = fma2(xv2, w0.y, a0h[n]);
                a1l[n] = fma2(xv2, w1.x, a1l[n]); a1h[n] = fma2(xv2, w1.y, a1h[n]);
                a2l[n] = fma2(xv2, w2.x, a2l[n]); a2h[n] = fma2(xv2, w2.y, a2h[n]);
            }
        }
    }
#pragma unroll
    for (int n = 0; n < 4; n++) {
        int node = n0 + n;
        if (node < NN) {
            float* o = g_so + (size_t)node * 384 + lane * 4;
            *(ulonglong2*)o         = make_ulonglong2(a0l[n], a0h[n]);
            *(ulonglong2*)(o + 128) = make_ulonglong2(a1l[n], a1h[n]);
            *(ulonglong2*)(o + 256) = make_ulonglong2(a2l[n], a2h[n]);
        }
    }
}

// ---------------- kernel 4: fused edge filter + gather + scatter (packed) ----
// 3 independent warps per edge; 384 threads (12 warps = 4 trios, 168-reg budget).
__global__ void __launch_bounds__(384, 1)
k_edge(const float* __restrict__ es, const float* __restrict__ ev,
       const float* __restrict__ en, const int* __restrict__ ei,
       const float* __restrict__ Wf, const float* __restrict__ bf,
       const float* __restrict__ nv, float* __restrict__ out) {
    int gwarp = (blockIdx.x * blockDim.x + threadIdx.x) >> 5;
    int lane = threadIdx.x & 31;
    int trio = gwarp / 3, role = gwarp % 3;
    const int step = (gridDim.x * 384 / 32) / 3;   // 592
    if (trio >= NE) return;

    float* out_s = out;
    float* out_v = out + (size_t)NN * D;

    if (role == 2) {
        // ---------- scalar path: cols 256..383, 2 packed pairs/lane ----------
        u64 W0[ESZ], W1[ESZ];
        {
            const float* wb = Wf + 256 + lane * 4;
#pragma unroll
            for (int k = 0; k < ESZ; k++) {
                ulonglong2 w = *(const ulonglong2*)(wb + k * 384);
                W0[k] = w.x; W1[k] = w.y;
            }
        }
        ulonglong2 bfr = *(const ulonglong2*)(bf + 256 + lane * 4);

        int e = trio;
        float esvA = (lane < ESZ) ? __ldg(es + (size_t)e * ESZ + lane) : 0.f;
        int2 sdA = __ldg((const int2*)ei + e);
        float rA = __ldg(en + e);

        int e1 = e + step;
        bool hasB = e1 < NE;
        float esvB = 0.f; int2 sdB = {0, 0}; float rB = 9.f;
        if (hasB) {
            esvB = (lane < ESZ) ? __ldg(es + (size_t)e1 * ESZ + lane) : 0.f;
            sdB = __ldg((const int2*)ei + e1);
            rB = __ldg(en + e1);
        }
        ulonglong2 soA = *(const ulonglong2*)(g_so + (size_t)sdA.x * 384 + 256 + lane * 4);

        while (true) {
            int e2 = e1 + step;
            float esvC = 0.f; int2 sdC = {0, 0}; float rC = 9.f;
            if (e2 < NE) {
                esvC = (lane < ESZ) ? __ldg(es + (size_t)e2 * ESZ + lane) : 0.f;
                sdC = __ldg((const int2*)ei + e2);
                rC = __ldg(en + e2);
            }
            ulonglong2 soB = make_ulonglong2(0, 0);
            if (hasB)
                soB = *(const ulonglong2*)(g_so + (size_t)sdB.x * 384 + 256 + lane * 4);

            float fc = (rA < 5.0f) ? 0.5f * (cospif(rA * 0.2f) + 1.0f) : 0.0f;
            u64 fc2 = pk2(fc, fc);
            u64 f0 = bfr.x, f1 = bfr.y;
#pragma unroll
            for (int k = 0; k < ESZ; k++) {
                float ek = __shfl_sync(0xffffffffu, esvA, k);
                u64 ek2 = pk2(ek, ek);
                f0 = fma2(ek2, W0[k], f0);
                f1 = fma2(ek2, W1[k], f1);
            }
            u64 m0 = mul2(mul2(f0, fc2), soA.x);
            u64 m1 = mul2(mul2(f1, fc2), soA.y);
            float x0, y0, x1, y1;
            upk2(m0, x0, y0); upk2(m1, x1, y1);
            red4(out_s + (size_t)sdA.y * D + lane * 4, x0, y0, x1, y1);

            if (!hasB) break;
            e = e1; e1 = e2;
            esvA = esvB; sdA = sdB; rA = rB; soA = soB;
            esvB = esvC; sdB = sdC; rB = rC;
            hasB = e1 < NE;
        }
    } else {
        // ---------- vector-half path: channels ch..ch+1 (one packed pair) ----
        int ch = role * 64 + lane * 2;
        u64 WN2[ESZ], WE2[ESZ];
#pragma unroll
        for (int k = 0; k < ESZ; k++) {
            WN2[k] = *(const u64*)(Wf + k * 384 + ch);
            WE2[k] = *(const u64*)(Wf + k * 384 + 128 + ch);
        }
        u64 bN2 = *(const u64*)(bf + ch);
        u64 bE2 = *(const u64*)(bf + 128 + ch);

        int e = trio;
        float esvA = (lane < ESZ) ? __ldg(es + (size_t)e * ESZ + lane) : 0.f;
        int2 sdA = __ldg((const int2*)ei + e);
        float rA = __ldg(en + e);

        int e1 = e + step;
        bool hasB = e1 < NE;
        float esvB = 0.f; int2 sdB = {0, 0}; float rB = 9.f;
        if (hasB) {
            esvB = (lane < ESZ) ? __ldg(es + (size_t)e1 * ESZ + lane) : 0.f;
            sdB = __ldg((const int2*)ei + e1);
            rB = __ldg(en + e1);
        }
        u64 soNA = *(const u64*)(g_so + (size_t)sdA.x * 384 + ch);
        u64 soEA = *(const u64*)(g_so + (size_t)sdA.x * 384 + 128 + ch);
        const float* nvbA = nv + (size_t)sdA.x * 384 + ch;
        u64 nA0 = *(const u64*)nvbA;
        u64 nA1 = *(const u64*)(nvbA + 128);
        u64 nA2 = *(const u64*)(nvbA + 256);
        float evA0 = __ldg(ev + 3 * (size_t)e);
        float evA1 = __ldg(ev + 3 * (size_t)e + 1);
        float evA2 = __ldg(ev + 3 * (size_t)e + 2);

        while (true) {
            int e2 = e1 + step;
            float esvC = 0.f; int2 sdC = {0, 0}; float rC = 9.f;
            if (e2 < NE) {
                esvC = (lane < ESZ) ? __ldg(es + (size_t)e2 * ESZ + lane) : 0.f;
                sdC = __ldg((const int2*)ei + e2);
                rC = __ldg(en + e2);
            }
            u64 soNB = 0, soEB = 0, nB0 = 0, nB1 = 0, nB2 = 0;
            float evB0 = 0.f, evB1 = 0.f, evB2 = 0.f;
            if (hasB) {
                soNB = *(const u64*)(g_so + (size_t)sdB.x * 384 + ch);
                soEB = *(const u64*)(g_so + (size_t)sdB.x * 384 + 128 + ch);
                const float* nvbB = nv + (size_t)sdB.x * 384 + ch;
                nB0 = *(const u64*)nvbB;
                nB1 = *(const u64*)(nvbB + 128);
                nB2 = *(const u64*)(nvbB + 256);
                evB0 = __ldg(ev + 3 * (size_t)e1);
                evB1 = __ldg(ev + 3 * (size_t)e1 + 1);
                evB2 = __ldg(ev + 3 * (size_t)e1 + 2);
            }
            float fc = (rA < 5.0f) ? 0.5f * (cospif(rA * 0.2f) + 1.0f) : 0.0f;
            u64 fc2 = pk2(fc, fc);
            u64 fN = bN2, fE = bE2;
#pragma unroll
            for (int k = 0; k < ESZ; k++) {
                float ek = __shfl_sync(0xffffffffu, esvA, k);
                u64 ek2 = pk2(ek, ek);
                fN = fma2(ek2, WN2[k], fN);
                fE = fma2(ek2, WE2[k], fE);
            }
            u64 gn = mul2(mul2(fN, fc2), soNA);
            u64 ge = mul2(mul2(fE, fc2), soEA);
            u64 m0 = fma2(gn, nA0, mul2(ge, pk2(evA0, evA0)));
            u64 m1 = fma2(gn, nA1, mul2(ge, pk2(evA1, evA1)));
            u64 m2 = fma2(gn, nA2, mul2(ge, pk2(evA2, evA2)));
            float* ovb = out_v + (size_t)sdA.y * 384 + ch;
            float l, h;
            upk2(m0, l, h); red2(ovb, l, h);
            upk2(m1, l, h); red2(ovb + 128, l, h);
            upk2(m2, l, h); red2(ovb + 256, l, h);

            if (!hasB) break;
            e = e1; e1 = e2;
            esvA = esvB; sdA = sdB; rA = rB;
            soNA = soNB; soEA = soEB;
            nA0 = nB0; nA1 = nB1; nA2 = nB2;
            evA0 = evB0; evA1 = evB1; evA2 = evB2;
            esvB = esvC; sdB = sdC; rB = rC;
            hasB = e1 < NE;
        }
    }
}

// ---------------- kernel 5: Uv, |Vv|^2, <Uv,Vv>  (packed) --------------------
__global__ void __launch_bounds__(512, 1)
k_uv(const float* __restrict__ WU, const float* __restrict__ WV,
     const float* __restrict__ out) {
    extern __shared__ float sm[];
    float* WUs = sm;
    float* WVs = sm + 16384;
    const float* v_in = out + (size_t)NN * D;
    int tid = threadIdx.x;
    {
        const float4* u4 = (const float4*)WU;
        const float4* v4 = (const float4*)WV;
        float4* su = (float4*)WUs;
        float4* sv = (float4*)WVs;
        for (int i = tid; i < 4096; i += 512) { su[i] = u4[i]; sv[i] = v4[i]; }
    }
    __syncthreads();
    int warp = tid >> 5, lane = tid & 31;
    int n0 = blockIdx.x * 32 + warp * 2;

    float xr[3][4][2];
#pragma unroll
    for (int n = 0; n < 2; n++) {
        int node = n0 + n;
#pragma unroll
        for (int ax = 0; ax < 3; ax++)
#pragma unroll
            for (int j = 0; j < 4; j++)
                xr[ax][j][n] = (node < NN)
                    ? v_in[(size_t)node * 384 + ax * 128 + j * 32 + lane] : 0.f;
    }
    u64 aUl[3][2], aUh[3][2], aVl[3][2], aVh[3][2];
#pragma unroll
    for (int ax = 0; ax < 3; ax++)
#pragma unroll
        for (int n = 0; n < 2; n++) {
            aUl[ax][n] = 0; aUh[ax][n] = 0;
            aVl[ax][n] = 0; aVh[ax][n] = 0;
        }

#pragma unroll
    for (int j = 0; j < 4; j++) {
#pragma unroll
        for (int kk = 0; kk < 32; kk++) {
            int k = j * 32 + kk;
            ulonglong2 wu = *(const ulonglong2*)(WUs + k * D + lane * 4);
            ulonglong2 wv = *(const ulonglong2*)(WVs + k * D + lane * 4);
#pragma unroll
            for (int n = 0; n < 2; n++) {
#pragma unroll
                for (int ax = 0; ax < 3; ax++) {
                    float v = __shfl_sync(0xffffffffu, xr[ax][j][n], kk);
                    u64 v2 = pk2(v, v);
                    aUl[ax][n] = fma2(v2, wu.x, aUl[ax][n]);
                    aUh[ax][n] = fma2(v2, wu.y, aUh[ax][n]);
                    aVl[ax][n] = fma2(v2, wv.x, aVl[ax][n]);
                    aVh[ax][n] = fma2(v2, wv.y, aVh[ax][n]);
                }
            }
        }
    }
#pragma unroll
    for (int n = 0; n < 2; n++) {
        int node = n0 + n;
        if (node < NN) {
            float u[3][4], vv[3][4];
#pragma unroll
            for (int ax = 0; ax < 3; ax++) {
                *(ulonglong2*)(g_uv + (size_t)node * 384 + ax * 128 + lane * 4)
                    = make_ulonglong2(aUl[ax][n], aUh[ax][n]);
                upk2(aUl[ax][n], u[ax][0], u[ax][1]);
                upk2(aUh[ax][n], u[ax][2], u[ax][3]);
                upk2(aVl[ax][n], vv[ax][0], vv[ax][1]);
                upk2(aVh[ax][n], vv[ax][2], vv[ax][3]);
            }
            float4 vq, ip;
            float* vqp = (float*)&vq;
            float* ipp = (float*)&ip;
#pragma unroll
            for (int c = 0; c < 4; c++) {
                vqp[c] = vv[0][c] * vv[0][c] + vv[1][c] * vv[1][c] + vv[2][c] * vv[2][c];
                ipp[c] = u[0][c] * vv[0][c] + u[1][c] * vv[1][c] + u[2][c] * vv[2][c];
            }
            *(float4*)(g_vvsq + (size_t)node * D + lane * 4) = vq;
            *(float4*)(g_ip + (size_t)node * D + lane * 4) = ip;
        }
    }
}

// ---------------- kernel 6: h2 = silu([s, Vvsq] @ Wa1 + ba1)  (packed) -------
__global__ void __launch_bounds__(512, 1)
k_a1(const float* __restrict__ W, const float* __restrict__ b,
     const float* __restrict__ out) {
    extern __shared__ float sm[];
    float* Ws = sm;                 // 32768
    float* bs = sm + 32768;         // 128
    int tid = threadIdx.x;
    {
        const float4* Wv = (const float4*)W;
        float4* Wsv = (float4*)Ws;
        for (int i = tid; i < 8192; i += 512) Wsv[i] = Wv[i];
        if (tid < 128) bs[tid] = b[tid];
    }
    __syncthreads();
    int warp = tid >> 5, lane = tid & 31;
    int n0 = blockIdx.x * 64 + warp * 4;

    float xr[8][4];
#pragma unroll
    for (int n = 0; n < 4; n++) {
        int node = n0 + n;
        if (node < NN) {
#pragma unroll
            for (int j = 0; j < 4; j++)
                xr[j][n] = out[(size_t)node * D + j * 32 + lane];
#pragma unroll
            for (int j = 0; j < 4; j++)
                xr[4 + j][n] = g_vvsq[(size_t)node * D + j * 32 + lane];
        } else {
#pragma unroll
            for (int j = 0; j < 8; j++) xr[j][n] = 0.f;
        }
    }
    ulonglong2 bv = *(const ulonglong2*)(bs + lane * 4);
    u64 al[4], ah[4];
#pragma unroll
    for (int n = 0; n < 4; n++) { al[n] = bv.x; ah[n] = bv.y; }

#pragma unroll
    for (int j = 0; j < 8; j++) {
#pragma unroll
        for (int kk = 0; kk < 32; kk++) {
            int k = j * 32 + kk;
            ulonglong2 w = *(const ulonglong2*)(Ws + k * D + lane * 4);
#pragma unroll
            for (int n = 0; n < 4; n++) {
                float xv = __shfl_sync(0xffffffffu, xr[j][n], kk);
                u64 xv2 = pk2(xv, xv);
                al[n] = fma2(xv2, w.x, al[n]);
                ah[n] = fma2(xv2, w.y, ah[n]);
            }
        }
    }
#pragma unroll
    for (int n = 0; n < 4; n++) {
        int node = n0 + n;
        if (node < NN) {
            float x0, x1, x2, x3;
            upk2(al[n], x0, x1); upk2(ah[n], x2, x3);
            float4 o;
            o.x = silu_f(x0); o.y = silu_f(x1);
            o.z = silu_f(x2); o.w = silu_f(x3);
            *(float4*)(g_h2 + (size_t)node * D + lane * 4) = o;
        }
    }
}

// ---------------- kernel 7: a = h2 @ Wa2 + ba2, final update  (packed) -------
__global__ void __launch_bounds__(512, 1)
k_a2(const float* __restrict__ W, const float* __restrict__ b,
     float* __restrict__ out) {
    extern __shared__ float sm[];
    float* Ws = sm;                 // 49152
    float* bs = sm + 49152;         // 384
    int tid = threadIdx.x;
    {
        const float4* Wv = (const float4*)W;
        float4* Wsv = (float4*)Ws;
        for (int i = tid; i < 12288; i += 512) Wsv[i] = Wv[i];
        if (tid < 384) bs[tid] = b[tid];
    }
    __syncthreads();
    int warp = tid >> 5, lane = tid & 31;
    int n0 = blockIdx.x * 64 + warp * 4;
    float* out_s = out;
    float* out_v = out + (size_t)NN * D;

    float xr[4][4];
#pragma unroll
    for (int n = 0; n < 4; n++) {
        int node = n0 + n;
#pragma unroll
        for (int j = 0; j < 4; j++)
            xr[j][n] = (node < NN) ? g_h2[(size_t)node * D + j * 32 + lane] : 0.f;
    }
    ulonglong2 b0 = *(const ulonglong2*)(bs + lane * 4);
    ulonglong2 b1 = *(const ulonglong2*)(bs + 128 + lane * 4);
    ulonglong2 b2 = *(const ulonglong2*)(bs + 256 + lane * 4);
    u64 a0l[4], a0h[4], a1l[4], a1h[4], a2l[4], a2h[4];
#pragma unroll
    for (int n = 0; n < 4; n++) {
        a0l[n] = b0.x; a0h[n] = b0.y;
        a1l[n] = b1.x; a1h[n] = b1.y;
        a2l[n] = b2.x; a2h[n] = b2.y;
    }

#pragma unroll
    for (int j = 0; j < 4; j++) {
#pragma unroll
        for (int kk = 0; kk < 32; kk++) {
            int k = j * 32 + kk;
            const float* wp = Ws + k * 384 + lane * 4;
            ulonglong2 w0 = *(const ulonglong2*)wp;
            ulonglong2 w1 = *(const ulonglong2*)(wp + 128);
            ulonglong2 w2 = *(const ulonglong2*)(wp + 256);
#pragma unroll
            for (int n = 0; n < 4; n++) {
                float xv = __shfl_sync(0xffffffffu, xr[j][n], kk);
                u64 xv2 = pk2(xv, xv);
                a0l[n] = fma2(xv2, w0.x, a0l[n]); a0h[n] = fma2(xv2, w0.y, a0h[n]);
                a1l[n] = fma2(xv2, w1.x, a1l[n]); a1h[n] = fma2(xv2, w1.y, a1h[n]);
                a2l[n] = fma2(xv2, w2.x, a2l[n]); a2h[n] = fma2(xv2, w2.y, a2h[n]);
            }
        }
    }
#pragma unroll
    for (int n = 0; n < 4; n++) {
        int node = n0 + n;
        if (node < NN) {
            float A0[4], A1[4], A2[4];
            upk2(a0l[n], A0[0], A0[1]); upk2(a0h[n], A0[2], A0[3]);
            upk2(a1l[n], A1[0], A1[1]); upk2(a1h[n], A1[2], A1[3]);
            upk2(a2l[n], A2[0], A2[1]); upk2(a2h[n], A2[2], A2[3]);
            float* sp = out_s + (size_t)node * D + lane * 4;
            float4 s = *(float4*)sp;
            float4 ip = *(float4*)(g_ip + (size_t)node * D + lane * 4);
            s.x += A0[0] + A1[0] * ip.x;
            s.y += A0[1] + A1[1] * ip.y;
            s.z += A0[2] + A1[2] * ip.z;
            s.w += A0[3] + A1[3] * ip.w;
            *(float4*)sp = s;
            const float* uvb = g_uv + (size_t)node * 384 + lane * 4;
            float* ovb = out_v + (size_t)node * 384 + lane * 4;
#pragma unroll
            for (int ax = 0; ax < 3; ax++) {
                float4 uv = *(const float4*)(uvb + ax * 128);
                float4 vv = *(float4*)(ovb + ax * 128);
                vv.x += A2[0] * uv.x;
                vv.y += A2[1] * uv.y;
                vv.z += A2[2] * uv.z;
                vv.w += A2[3] * uv.w;
                *(float4*)(ovb + ax * 128) = vv;
            }
        }
    }
}

// ---------------- launch ------------------------------------------------------
extern "C" void kernel_launch(void* const* d_in, const int* in_sizes, int n_in,
                              void* d_out, int out_size) {
    const float* ns  = (const float*)d_in[0];
    const float* nv  = (const float*)d_in[1];
    const float* es  = (const float*)d_in[2];
    const float* ev  = (const float*)d_in[3];
    const float* en  = (const float*)d_in[4];
    const int*   ei  = (const int*)d_in[5];
    const float* Wf  = (const float*)d_in[6];
    const float* bf  = (const float*)d_in[7];
    const float* Wm1 = (const float*)d_in[8];
    const float* bm1 = (const float*)d_in[9];
    const float* Wm2 = (const float*)d_in[10];
    const float* bm2 = (const float*)d_in[11];
    const float* WU  = (const float*)d_in[12];
    const float* WV  = (const float*)d_in[13];
    const float* Wa1 = (const float*)d_in[14];
    const float* ba1 = (const float*)d_in[15];
    const float* Wa2 = (const float*)d_in[16];
    const float* ba2 = (const float*)d_in[17];
    float* out = (float*)d_out;

    const int SM_MLP1 = (16384 + 128) * 4;
    const int SM_GEMM = (49152 + 384) * 4;
    const int SM_UV   = 32768 * 4;
    const int SM_A1   = (32768 + 128) * 4;

    cudaFuncSetAttribute(k_mlp1, cudaFuncAttributeMaxDynamicSharedMemorySize, SM_MLP1);
    cudaFuncSetAttribute(k_mlp2, cudaFuncAttributeMaxDynamicSharedMemorySize, SM_GEMM);
    cudaFuncSetAttribute(k_uv,   cudaFuncAttributeMaxDynamicSharedMemorySize, SM_UV);
    cudaFuncSetAttribute(k_a1,   cudaFuncAttributeMaxDynamicSharedMemorySize, SM_A1);
    cudaFuncSetAttribute(k_a2,   cudaFuncAttributeMaxDynamicSharedMemorySize, SM_GEMM);

    int gnode = (NN + 63) / 64;   // 313
    int guv   = (NN + 31) / 32;   // 625

    k_init<<<2048, 256>>>(ns, nv, out);
    k_mlp1<<<gnode, 512, SM_MLP1>>>(ns, Wm1, bm1);
    k_mlp2<<<gnode, 512, SM_GEMM>>>(Wm2, bm2);
    k_edge<<<148, 384>>>(es, ev, en, ei, Wf, bf, nv, out);
    k_uv<<<guv, 512, SM_UV>>>(WU, WV, out);
    k_a1<<<gnode, 512, SM_A1>>>(Wa1, ba1, out);
    k_a2<<<gnode, 512, SM_GEMM>>>(Wa2, ba2, out);
}